// round 3
// baseline (speedup 1.0000x reference)
#include <cuda_runtime.h>
#include <math.h>

#define B_   2
#define S_   2048
#define D_   2048
#define QH_  32
#define KVH_ 8
#define HD_  64
#define GRP_ 4

// ---------------- scratch (no allocations allowed) ----------------
__device__ float g_Q [(size_t)B_ * S_ * QH_  * HD_];   // 33.5 MB
__device__ float g_K [(size_t)B_ * S_ * KVH_ * HD_];   //  8.4 MB
__device__ float g_V [(size_t)B_ * S_ * KVH_ * HD_];   //  8.4 MB
__device__ float g_AO[(size_t)B_ * S_ * QH_  * HD_];   // 33.5 MB

// ---------------- generic fp32 GEMM + bias: C[M,N] = A[M,K] @ W[K,N] + b ----
// 128x128x16 tile, 256 threads, 8x8 microtile.
__global__ __launch_bounds__(256, 2)
void gemm_bias(const float* __restrict__ A, const float* __restrict__ W,
               const float* __restrict__ bias, float* __restrict__ C,
               int M, int N, int K)
{
    __shared__ float As[16][132];   // As[k][m], padded to dodge store conflicts
    __shared__ float Ws[16][128];   // Ws[k][n]

    const int t  = threadIdx.x;
    const int m0 = blockIdx.y * 128;
    const int n0 = blockIdx.x * 128;
    const int tx = t & 15;          // 0..15  -> 8 cols each
    const int ty = t >> 4;          // 0..15  -> 8 rows each

    // A loader: 2 float4 per thread
    const int arow = t >> 2;        // 0..63
    const int avec = (t & 3) * 4;   // k offset 0,4,8,12
    // W loader: 2 float4 per thread
    const int wrow = t >> 5;        // 0..7
    const int wcol = (t & 31) * 4;  // 0..124

    float acc[8][8];
#pragma unroll
    for (int i = 0; i < 8; i++)
#pragma unroll
        for (int j = 0; j < 8; j++) acc[i][j] = 0.f;

    for (int k0 = 0; k0 < K; k0 += 16) {
        float4 a0 = *(const float4*)&A[(size_t)(m0 + arow)      * K + k0 + avec];
        float4 a1 = *(const float4*)&A[(size_t)(m0 + arow + 64) * K + k0 + avec];
        float4 w0 = *(const float4*)&W[(size_t)(k0 + wrow)     * N + n0 + wcol];
        float4 w1 = *(const float4*)&W[(size_t)(k0 + wrow + 8) * N + n0 + wcol];

        As[avec + 0][arow] = a0.x;  As[avec + 1][arow] = a0.y;
        As[avec + 2][arow] = a0.z;  As[avec + 3][arow] = a0.w;
        As[avec + 0][arow + 64] = a1.x;  As[avec + 1][arow + 64] = a1.y;
        As[avec + 2][arow + 64] = a1.z;  As[avec + 3][arow + 64] = a1.w;
        *(float4*)&Ws[wrow][wcol]     = w0;
        *(float4*)&Ws[wrow + 8][wcol] = w1;
        __syncthreads();

#pragma unroll
        for (int kk = 0; kk < 16; kk++) {
            float af[8], bf[8];
#pragma unroll
            for (int i = 0; i < 8; i++) af[i] = As[kk][ty * 8 + i];
#pragma unroll
            for (int j = 0; j < 8; j++) bf[j] = Ws[kk][tx * 8 + j];
#pragma unroll
            for (int i = 0; i < 8; i++)
#pragma unroll
                for (int j = 0; j < 8; j++) acc[i][j] += af[i] * bf[j];
        }
        __syncthreads();
    }

#pragma unroll
    for (int i = 0; i < 8; i++) {
        const int row = m0 + ty * 8 + i;
#pragma unroll
        for (int j = 0; j < 8; j += 4) {
            const int col = n0 + tx * 8 + j;
            float4 o;
            o.x = acc[i][j + 0] + bias[col + 0];
            o.y = acc[i][j + 1] + bias[col + 1];
            o.z = acc[i][j + 2] + bias[col + 2];
            o.w = acc[i][j + 3] + bias[col + 3];
            *(float4*)&C[(size_t)row * N + col] = o;
        }
    }
}

// ---------------- RoPE (in place) on [B,S,H,64]; freqs [S,32,2] ------------
__global__ void rope_kernel(float* __restrict__ X, const float* __restrict__ F,
                            int hshift /* log2(H) */, int total_pairs)
{
    int idx = blockIdx.x * blockDim.x + threadIdx.x;
    if (idx >= total_pairs) return;
    int p = idx & 31;
    int s = (idx >> (5 + hshift)) & (S_ - 1);
    float2 cs = ((const float2*)F)[s * 32 + p];
    float2 x  = ((float2*)X)[idx];
    float2 o;
    o.x = x.x * cs.x - x.y * cs.y;
    o.y = x.x * cs.y + x.y * cs.x;
    ((float2*)X)[idx] = o;
}

// ---------------- flash attention, fp32, one query row per thread ----------
// grid (S/128, QH, B), block 128. dyn smem: Ks 64x64, Vs 64x64, Sc 64x128.
__global__ __launch_bounds__(128, 3)
void attn_kernel(const float* __restrict__ Q, const float* __restrict__ K,
                 const float* __restrict__ V, float* __restrict__ O)
{
    extern __shared__ float sm[];
    float* Ks = sm;             // [64][64]
    float* Vs = sm + 4096;      // [64][64]
    float* Sc = sm + 8192;      // [64][128] per-thread score spill

    const int tid = threadIdx.x;
    const int h   = blockIdx.y;
    const int b   = blockIdx.z;
    const int kh  = h >> 2;                      // GQA: 4 q heads per kv head
    const int qrow = blockIdx.x * 128 + tid;

    const float* qp = Q + ((size_t)(b * S_ + qrow) * QH_ + h) * HD_;
    float q[64];
#pragma unroll
    for (int i = 0; i < 16; i++) ((float4*)q)[i] = ((const float4*)qp)[i];

    float acc[64];
#pragma unroll
    for (int i = 0; i < 64; i++) acc[i] = 0.f;
    float mrow = -1e30f, lrow = 0.f;
    const float scale = 0.125f;                  // 1/sqrt(64)

    const float* kb = K + (size_t)b * S_ * KVH_ * HD_ + kh * HD_;
    const float* vb = V + (size_t)b * S_ * KVH_ * HD_ + kh * HD_;

    for (int kt = 0; kt < S_ / 64; kt++) {
        const float* kp = kb + (size_t)kt * 64 * KVH_ * HD_;
        const float* vp = vb + (size_t)kt * 64 * KVH_ * HD_;
        for (int e = tid; e < 4096; e += 128) {
            int r = e >> 6, c = e & 63;
            Ks[e] = kp[r * (KVH_ * HD_) + c];
            Vs[e] = vp[r * (KVH_ * HD_) + c];
        }
        __syncthreads();

        float tmax = -1e30f;
#pragma unroll 1
        for (int j = 0; j < 64; j++) {
            float s0 = 0.f, s1 = 0.f, s2 = 0.f, s3 = 0.f;
            const float4* krow = (const float4*)(Ks + j * 64);
#pragma unroll
            for (int d4 = 0; d4 < 16; d4++) {
                float4 kv = krow[d4];                    // warp-broadcast LDS
                s0 += q[d4 * 4 + 0] * kv.x;
                s1 += q[d4 * 4 + 1] * kv.y;
                s2 += q[d4 * 4 + 2] * kv.z;
                s3 += q[d4 * 4 + 3] * kv.w;
            }
            float s = ((s0 + s1) + (s2 + s3)) * scale;
            Sc[j * 128 + tid] = s;
            tmax = fmaxf(tmax, s);
        }

        float mnew = fmaxf(mrow, tmax);
        float corr = __expf(mrow - mnew);
        lrow *= corr;
#pragma unroll
        for (int d = 0; d < 64; d++) acc[d] *= corr;

#pragma unroll 1
        for (int j = 0; j < 64; j++) {
            float w = __expf(Sc[j * 128 + tid] - mnew);
            lrow += w;
            const float4* vrow = (const float4*)(Vs + j * 64);
#pragma unroll
            for (int d4 = 0; d4 < 16; d4++) {
                float4 vv = vrow[d4];                    // warp-broadcast LDS
                acc[d4 * 4 + 0] += w * vv.x;
                acc[d4 * 4 + 1] += w * vv.y;
                acc[d4 * 4 + 2] += w * vv.z;
                acc[d4 * 4 + 3] += w * vv.w;
            }
        }
        mrow = mnew;
        __syncthreads();
    }

    const float inv = 1.0f / lrow;
    float* op = O + ((size_t)(b * S_ + qrow) * QH_ + h) * HD_;
#pragma unroll
    for (int d4 = 0; d4 < 16; d4++) {
        float4 o;
        o.x = acc[d4 * 4 + 0] * inv;
        o.y = acc[d4 * 4 + 1] * inv;
        o.z = acc[d4 * 4 + 2] * inv;
        o.w = acc[d4 * 4 + 3] * inv;
        ((float4*)op)[d4] = o;
    }
}

// ---------------------------------------------------------------------------
extern "C" void kernel_launch(void* const* d_in, const int* in_sizes, int n_in,
                              void* d_out, int out_size)
{
    const float* x  = (const float*)d_in[0];
    const float* fr = (const float*)d_in[1];
    const float* Wq = (const float*)d_in[2];
    const float* bq = (const float*)d_in[3];
    const float* Wk = (const float*)d_in[4];
    const float* bk = (const float*)d_in[5];
    const float* Wv = (const float*)d_in[6];
    const float* bv = (const float*)d_in[7];
    const float* Wo = (const float*)d_in[8];
    const float* bo = (const float*)d_in[9];
    float* out = (float*)d_out;

    float *Qp, *Kp, *Vp, *AOp;
    cudaGetSymbolAddress((void**)&Qp,  g_Q);
    cudaGetSymbolAddress((void**)&Kp,  g_K);
    cudaGetSymbolAddress((void**)&Vp,  g_V);
    cudaGetSymbolAddress((void**)&AOp, g_AO);

    const int M = B_ * S_;   // 4096

    // Q/K/V projections
    gemm_bias<<<dim3((QH_ * HD_) / 128, M / 128), 256>>>(x, Wq, bq, Qp, M, QH_ * HD_, D_);
    gemm_bias<<<dim3((KVH_ * HD_) / 128, M / 128), 256>>>(x, Wk, bk, Kp, M, KVH_ * HD_, D_);
    gemm_bias<<<dim3((KVH_ * HD_) / 128, M / 128), 256>>>(x, Wv, bv, Vp, M, KVH_ * HD_, D_);

    // RoPE on Q and K
    {
        int totq = M * QH_ * 32;
        rope_kernel<<<totq / 256, 256>>>(Qp, fr, 5 /*log2(32)*/, totq);
        int totk = M * KVH_ * 32;
        rope_kernel<<<totk / 256, 256>>>(Kp, fr, 3 /*log2(8)*/, totk);
    }

    // attention
    cudaFuncSetAttribute(attn_kernel, cudaFuncAttributeMaxDynamicSharedMemorySize, 65536);
    attn_kernel<<<dim3(S_ / 128, QH_, B_), 128, 65536>>>(Qp, Kp, Vp, AOp);

    // output projection
    gemm_bias<<<dim3(D_ / 128, M / 128), 256>>>(AOp, Wo, bo, out, M, D_, D_);
}

// round 4
// speedup vs baseline: 1.4343x; 1.4343x over previous
#include <cuda_runtime.h>
#include <mma.h>
#include <math.h>

using namespace nvcuda;

#define B_   2
#define S_   2048
#define D_   2048
#define QH_  32
#define KVH_ 8
#define HD_  64
#define GRP_ 4

// ---------------- scratch (no allocations allowed) ----------------
__device__ float g_Q [(size_t)B_ * S_ * QH_  * HD_];
__device__ float g_K [(size_t)B_ * S_ * KVH_ * HD_];
__device__ float g_V [(size_t)B_ * S_ * KVH_ * HD_];
__device__ float g_AO[(size_t)B_ * S_ * QH_  * HD_];

// ===================== TF32 GEMM + bias ====================================
// C[M,N] = A[M,K] @ W[K,N] + b.  128x128 block tile, BK=32, 8 warps,
// warp tile 64x32 = 4x2 wmma m16n16k8 fragments. fp32 accumulate.
__global__ __launch_bounds__(256)
void gemm_tf32(const float* __restrict__ A, const float* __restrict__ W,
               const float* __restrict__ bias, float* __restrict__ C,
               int M, int N, int K)
{
    __shared__ float As[128 * 36];     // [m][k], ld 36
    __shared__ float Bs[32 * 132];     // [k][n], ld 132
    __shared__ float Bt[16 * 132];     // replicated bias rows

    const int t      = threadIdx.x;
    const int warp   = t >> 5;
    const int warp_m = warp & 1;       // 0..1  -> 64 rows
    const int warp_n = warp >> 1;      // 0..3  -> 32 cols
    const int m0 = blockIdx.y * 128;
    const int n0 = blockIdx.x * 128;

    // loaders
    const int arow = t >> 2;           // 0..63 (two rows: arow, arow+64)
    const int avec = (t & 3) * 8;      // k offset 0,8,16,24
    const int wrow = t >> 5;           // 0..7 (rows wrow, wrow+8, +16, +24)
    const int wcol = (t & 31) * 4;

    // bias tile: 16 identical rows of bias[n0..n0+127]
    for (int e = t; e < 16 * 128; e += 256) {
        int r = e >> 7, c = e & 127;
        Bt[r * 132 + c] = bias[n0 + c];
    }
    __syncthreads();

    wmma::fragment<wmma::accumulator, 16, 16, 8, float> acc[4][2];
#pragma unroll
    for (int i = 0; i < 4; i++)
#pragma unroll
        for (int j = 0; j < 2; j++)
            wmma::load_matrix_sync(acc[i][j], &Bt[warp_n * 32 + j * 16], 132,
                                   wmma::mem_row_major);

    for (int k0 = 0; k0 < K; k0 += 32) {
        // load A tile: each thread 2x float4 pairs (8 floats over 2 rows)
        float4 a0 = *(const float4*)&A[(size_t)(m0 + arow)      * K + k0 + avec];
        float4 a1 = *(const float4*)&A[(size_t)(m0 + arow)      * K + k0 + avec + 4];
        float4 a2 = *(const float4*)&A[(size_t)(m0 + arow + 64) * K + k0 + avec];
        float4 a3 = *(const float4*)&A[(size_t)(m0 + arow + 64) * K + k0 + avec + 4];
        // load W tile: rows wrow, wrow+8, +16, +24
        float4 w0 = *(const float4*)&W[(size_t)(k0 + wrow)      * N + n0 + wcol];
        float4 w1 = *(const float4*)&W[(size_t)(k0 + wrow +  8) * N + n0 + wcol];
        float4 w2 = *(const float4*)&W[(size_t)(k0 + wrow + 16) * N + n0 + wcol];
        float4 w3 = *(const float4*)&W[(size_t)(k0 + wrow + 24) * N + n0 + wcol];

        *(float4*)&As[arow * 36 + avec]            = a0;
        *(float4*)&As[arow * 36 + avec + 4]        = a1;
        *(float4*)&As[(arow + 64) * 36 + avec]     = a2;
        *(float4*)&As[(arow + 64) * 36 + avec + 4] = a3;
        *(float4*)&Bs[wrow * 132 + wcol]           = w0;
        *(float4*)&Bs[(wrow +  8) * 132 + wcol]    = w1;
        *(float4*)&Bs[(wrow + 16) * 132 + wcol]    = w2;
        *(float4*)&Bs[(wrow + 24) * 132 + wcol]    = w3;
        __syncthreads();

#pragma unroll
        for (int kk = 0; kk < 32; kk += 8) {
            wmma::fragment<wmma::matrix_a, 16, 16, 8, wmma::precision::tf32,
                           wmma::row_major> af[4];
            wmma::fragment<wmma::matrix_b, 16, 16, 8, wmma::precision::tf32,
                           wmma::row_major> bf[2];
#pragma unroll
            for (int i = 0; i < 4; i++) {
                wmma::load_matrix_sync(af[i],
                    &As[(warp_m * 64 + i * 16) * 36 + kk], 36);
#pragma unroll
                for (int e = 0; e < af[i].num_elements; e++)
                    af[i].x[e] = wmma::__float_to_tf32(af[i].x[e]);
            }
#pragma unroll
            for (int j = 0; j < 2; j++) {
                wmma::load_matrix_sync(bf[j],
                    &Bs[kk * 132 + warp_n * 32 + j * 16], 132);
#pragma unroll
                for (int e = 0; e < bf[j].num_elements; e++)
                    bf[j].x[e] = wmma::__float_to_tf32(bf[j].x[e]);
            }
#pragma unroll
            for (int i = 0; i < 4; i++)
#pragma unroll
                for (int j = 0; j < 2; j++)
                    wmma::mma_sync(acc[i][j], af[i], bf[j], acc[i][j]);
        }
        __syncthreads();
    }

#pragma unroll
    for (int i = 0; i < 4; i++)
#pragma unroll
        for (int j = 0; j < 2; j++)
            wmma::store_matrix_sync(
                &C[(size_t)(m0 + warp_m * 64 + i * 16) * N
                   + n0 + warp_n * 32 + j * 16],
                acc[i][j], N, wmma::mem_row_major);
}

// ---------------- RoPE (in place) on [B,S,H,64]; freqs [S,32,2] ------------
__global__ void rope_kernel(float* __restrict__ X, const float* __restrict__ F,
                            int hshift, int total_pairs)
{
    int idx = blockIdx.x * blockDim.x + threadIdx.x;
    if (idx >= total_pairs) return;
    int p = idx & 31;
    int s = (idx >> (5 + hshift)) & (S_ - 1);
    float2 cs = ((const float2*)F)[s * 32 + p];
    float2 x  = ((float2*)X)[idx];
    float2 o;
    o.x = x.x * cs.x - x.y * cs.y;
    o.y = x.x * cs.y + x.y * cs.x;
    ((float2*)X)[idx] = o;
}

// ===================== TF32 flash attention ================================
// grid (S/64, QH, B), 128 threads (4 warps). 64 q-rows per block.
// smem: Qs,Ks,Vs,Sc,Os each [64][72] fp32.
#define ALD 72
__global__ __launch_bounds__(128)
void attn_tf32(const float* __restrict__ Q, const float* __restrict__ K,
               const float* __restrict__ V, float* __restrict__ O)
{
    extern __shared__ float sm[];
    float* Qs = sm;
    float* Ks = sm + 64 * ALD;
    float* Vs = sm + 2 * 64 * ALD;
    float* Sc = sm + 3 * 64 * ALD;
    float* Os = sm + 4 * 64 * ALD;
    __shared__ float rowm[64], rowl[64], rowc[64];

    const int tid = threadIdx.x;
    const int w   = tid >> 5;
    const int h   = blockIdx.y;
    const int b   = blockIdx.z;
    const int kh  = h >> 2;
    const int q0  = blockIdx.x * 64;

    // load Q tile, zero O tile
    const float* qbase = Q + ((size_t)(b * S_ + q0) * QH_ + h) * HD_;
    for (int e4 = tid; e4 < 1024; e4 += 128) {
        int r = e4 >> 4, c4 = (e4 & 15) * 4;
        *(float4*)&Qs[r * ALD + c4] = *(const float4*)&qbase[(size_t)r * (QH_ * HD_) + c4];
        *(float4*)&Os[r * ALD + c4] = make_float4(0.f, 0.f, 0.f, 0.f);
    }
    if (tid < 64) { rowm[tid] = -1e30f; rowl[tid] = 0.f; }
    __syncthreads();

    const float* kb = K + (size_t)b * S_ * KVH_ * HD_ + kh * HD_;
    const float* vb = V + (size_t)b * S_ * KVH_ * HD_ + kh * HD_;

    for (int kt = 0; kt < S_ / 64; kt++) {
        const float* kp = kb + (size_t)kt * 64 * (KVH_ * HD_);
        const float* vp = vb + (size_t)kt * 64 * (KVH_ * HD_);
        for (int e4 = tid; e4 < 1024; e4 += 128) {
            int r = e4 >> 4, c4 = (e4 & 15) * 4;
            *(float4*)&Ks[r * ALD + c4] = *(const float4*)&kp[(size_t)r * (KVH_ * HD_) + c4];
            *(float4*)&Vs[r * ALD + c4] = *(const float4*)&vp[(size_t)r * (KVH_ * HD_) + c4];
        }
        __syncthreads();

        // ---- S = Q K^T * scale : warp w -> rows w*16..w*16+15, 64 cols ----
        {
            wmma::fragment<wmma::accumulator, 16, 16, 8, float> sacc[4];
#pragma unroll
            for (int j = 0; j < 4; j++) wmma::fill_fragment(sacc[j], 0.f);
#pragma unroll
            for (int kk = 0; kk < 64; kk += 8) {
                wmma::fragment<wmma::matrix_a, 16, 16, 8, wmma::precision::tf32,
                               wmma::row_major> af;
                wmma::load_matrix_sync(af, &Qs[w * 16 * ALD + kk], ALD);
#pragma unroll
                for (int e = 0; e < af.num_elements; e++)
                    af.x[e] = wmma::__float_to_tf32(af.x[e]);
#pragma unroll
                for (int j = 0; j < 4; j++) {
                    wmma::fragment<wmma::matrix_b, 16, 16, 8, wmma::precision::tf32,
                                   wmma::col_major> bf;
                    wmma::load_matrix_sync(bf, &Ks[j * 16 * ALD + kk], ALD);
#pragma unroll
                    for (int e = 0; e < bf.num_elements; e++)
                        bf.x[e] = wmma::__float_to_tf32(bf.x[e]);
                    wmma::mma_sync(sacc[j], af, bf, sacc[j]);
                }
            }
#pragma unroll
            for (int j = 0; j < 4; j++) {
#pragma unroll
                for (int e = 0; e < sacc[j].num_elements; e++)
                    sacc[j].x[e] *= 0.125f;
                wmma::store_matrix_sync(&Sc[w * 16 * ALD + j * 16], sacc[j], ALD,
                                        wmma::mem_row_major);
            }
        }
        __syncthreads();

        // ---- online softmax on rows (one thread per row) ----
        if (tid < 64) {
            float* rp = &Sc[tid * ALD];
            float tmax = -1e30f;
#pragma unroll
            for (int c = 0; c < 64; c++) tmax = fmaxf(tmax, rp[c]);
            float mold = rowm[tid];
            float mnew = fmaxf(mold, tmax);
            float corr = __expf(mold - mnew);
            float sum = 0.f;
#pragma unroll
            for (int c = 0; c < 64; c++) {
                float p = __expf(rp[c] - mnew);
                rp[c] = p;
                sum += p;
            }
            rowl[tid] = rowl[tid] * corr + sum;
            rowm[tid] = mnew;
            rowc[tid] = corr;
        }
        __syncthreads();

        // ---- rescale O accumulator ----
        for (int e4 = tid; e4 < 1024; e4 += 128) {
            int r = e4 >> 4, c4 = (e4 & 15) * 4;
            float cr = rowc[r];
            float4 o = *(float4*)&Os[r * ALD + c4];
            o.x *= cr; o.y *= cr; o.z *= cr; o.w *= cr;
            *(float4*)&Os[r * ALD + c4] = o;
        }
        __syncthreads();

        // ---- O += P V ----
        {
            wmma::fragment<wmma::accumulator, 16, 16, 8, float> oacc[4];
#pragma unroll
            for (int j = 0; j < 4; j++)
                wmma::load_matrix_sync(oacc[j], &Os[w * 16 * ALD + j * 16], ALD,
                                       wmma::mem_row_major);
#pragma unroll
            for (int kk = 0; kk < 64; kk += 8) {
                wmma::fragment<wmma::matrix_a, 16, 16, 8, wmma::precision::tf32,
                               wmma::row_major> af;
                wmma::load_matrix_sync(af, &Sc[w * 16 * ALD + kk], ALD);
#pragma unroll
                for (int e = 0; e < af.num_elements; e++)
                    af.x[e] = wmma::__float_to_tf32(af.x[e]);
#pragma unroll
                for (int j = 0; j < 4; j++) {
                    wmma::fragment<wmma::matrix_b, 16, 16, 8, wmma::precision::tf32,
                                   wmma::row_major> bf;
                    wmma::load_matrix_sync(bf, &Vs[kk * ALD + j * 16], ALD);
#pragma unroll
                    for (int e = 0; e < bf.num_elements; e++)
                        bf.x[e] = wmma::__float_to_tf32(bf.x[e]);
                    wmma::mma_sync(oacc[j], af, bf, oacc[j]);
                }
            }
#pragma unroll
            for (int j = 0; j < 4; j++)
                wmma::store_matrix_sync(&Os[w * 16 * ALD + j * 16], oacc[j], ALD,
                                        wmma::mem_row_major);
        }
        __syncthreads();
    }

    // ---- finalize: divide by l, write out ----
    float* obase = O + ((size_t)(b * S_ + q0) * QH_ + h) * HD_;
    for (int e4 = tid; e4 < 1024; e4 += 128) {
        int r = e4 >> 4, c4 = (e4 & 15) * 4;
        float inv = 1.0f / rowl[r];
        float4 o = *(float4*)&Os[r * ALD + c4];
        o.x *= inv; o.y *= inv; o.z *= inv; o.w *= inv;
        *(float4*)&obase[(size_t)r * (QH_ * HD_) + c4] = o;
    }
}

// ---------------------------------------------------------------------------
extern "C" void kernel_launch(void* const* d_in, const int* in_sizes, int n_in,
                              void* d_out, int out_size)
{
    const float* x  = (const float*)d_in[0];
    const float* fr = (const float*)d_in[1];
    const float* Wq = (const float*)d_in[2];
    const float* bq = (const float*)d_in[3];
    const float* Wk = (const float*)d_in[4];
    const float* bk = (const float*)d_in[5];
    const float* Wv = (const float*)d_in[6];
    const float* bv = (const float*)d_in[7];
    const float* Wo = (const float*)d_in[8];
    const float* bo = (const float*)d_in[9];
    float* out = (float*)d_out;

    float *Qp, *Kp, *Vp, *AOp;
    cudaGetSymbolAddress((void**)&Qp,  g_Q);
    cudaGetSymbolAddress((void**)&Kp,  g_K);
    cudaGetSymbolAddress((void**)&Vp,  g_V);
    cudaGetSymbolAddress((void**)&AOp, g_AO);

    const int M = B_ * S_;   // 4096

    gemm_tf32<<<dim3((QH_ * HD_) / 128, M / 128), 256>>>(x, Wq, bq, Qp, M, QH_ * HD_, D_);
    gemm_tf32<<<dim3((KVH_ * HD_) / 128, M / 128), 256>>>(x, Wk, bk, Kp, M, KVH_ * HD_, D_);
    gemm_tf32<<<dim3((KVH_ * HD_) / 128, M / 128), 256>>>(x, Wv, bv, Vp, M, KVH_ * HD_, D_);

    {
        int totq = M * QH_ * 32;
        rope_kernel<<<totq / 256, 256>>>(Qp, fr, 5, totq);
        int totk = M * KVH_ * 32;
        rope_kernel<<<totk / 256, 256>>>(Kp, fr, 3, totk);
    }

    static int smem_set = 0;
    size_t attn_smem = (size_t)5 * 64 * ALD * sizeof(float);
    cudaFuncSetAttribute(attn_tf32, cudaFuncAttributeMaxDynamicSharedMemorySize,
                         (int)attn_smem);
    (void)smem_set;
    attn_tf32<<<dim3(S_ / 64, QH_, B_), 128, attn_smem>>>(Qp, Kp, Vp, AOp);

    gemm_tf32<<<dim3(D_ / 128, M / 128), 256>>>(AOp, Wo, bo, out, M, D_, D_);
}

// round 7
// speedup vs baseline: 1.5453x; 1.0774x over previous
#include <cuda_runtime.h>
#include <cstdint>
#include <mma.h>
#include <math.h>

using namespace nvcuda;

#define B_   2
#define S_   2048
#define D_   2048
#define QH_  32
#define KVH_ 8
#define HD_  64
#define GRP_ 4

// ---------------- scratch (no allocations allowed) ----------------
__device__ float g_Q [(size_t)B_ * S_ * QH_  * HD_];
__device__ float g_K [(size_t)B_ * S_ * KVH_ * HD_];
__device__ float g_V [(size_t)B_ * S_ * KVH_ * HD_];
__device__ float g_AO[(size_t)B_ * S_ * QH_  * HD_];

// ---------------- cp.async helpers ----------------
__device__ __forceinline__ void cpa16(void* smem_dst, const void* gmem_src) {
    unsigned d = (unsigned)__cvta_generic_to_shared(smem_dst);
    asm volatile("cp.async.cg.shared.global [%0], [%1], 16;\n" :: "r"(d), "l"(gmem_src));
}
#define CP_COMMIT() asm volatile("cp.async.commit_group;\n" ::: "memory")
#define CP_WAIT0()  asm volatile("cp.async.wait_group 0;\n" ::: "memory")
#define CP_WAIT1()  asm volatile("cp.async.wait_group 1;\n" ::: "memory")

// ===================== TF32 GEMM + bias, double-buffered ===================
// C[M,N] = A[M,K] @ W[K,N] + b. 128x128 tile, BK=32, 8 warps, warp 64x32.
#define GA_SZ (128 * 36)
#define GB_SZ (32 * 132)
__global__ __launch_bounds__(256)
void gemm_tf32(const float* __restrict__ A, const float* __restrict__ W,
               const float* __restrict__ bias, float* __restrict__ C,
               int M, int N, int K)
{
    extern __shared__ float dsm[];
    float* As = dsm;                  // [2][128][36]
    float* Bs = dsm + 2 * GA_SZ;      // [2][32][132]
    __shared__ float Bt[16 * 132];

    const int t      = threadIdx.x;
    const int warp   = t >> 5;
    const int warp_m = warp & 1;
    const int warp_n = warp >> 1;
    const int m0 = blockIdx.y * 128;
    const int n0 = blockIdx.x * 128;

    const int arow = t >> 2;
    const int avec = (t & 3) * 8;
    const int wrow = t >> 5;
    const int wcol = (t & 31) * 4;

    for (int e = t; e < 16 * 128; e += 256) {
        int r = e >> 7, c = e & 127;
        Bt[r * 132 + c] = bias[n0 + c];
    }

    wmma::fragment<wmma::accumulator, 16, 16, 8, float> acc[4][2];
    __syncthreads();
#pragma unroll
    for (int i = 0; i < 4; i++)
#pragma unroll
        for (int j = 0; j < 2; j++)
            wmma::load_matrix_sync(acc[i][j], &Bt[warp_n * 32 + j * 16], 132,
                                   wmma::mem_row_major);

    auto load_tile = [&](int k0, int buf) {
        float* Ab = As + buf * GA_SZ;
        float* Bb = Bs + buf * GB_SZ;
        cpa16(&Ab[arow * 36 + avec],            &A[(size_t)(m0 + arow)      * K + k0 + avec]);
        cpa16(&Ab[arow * 36 + avec + 4],        &A[(size_t)(m0 + arow)      * K + k0 + avec + 4]);
        cpa16(&Ab[(arow + 64) * 36 + avec],     &A[(size_t)(m0 + arow + 64) * K + k0 + avec]);
        cpa16(&Ab[(arow + 64) * 36 + avec + 4], &A[(size_t)(m0 + arow + 64) * K + k0 + avec + 4]);
        cpa16(&Bb[wrow * 132 + wcol],           &W[(size_t)(k0 + wrow)      * N + n0 + wcol]);
        cpa16(&Bb[(wrow +  8) * 132 + wcol],    &W[(size_t)(k0 + wrow +  8) * N + n0 + wcol]);
        cpa16(&Bb[(wrow + 16) * 132 + wcol],    &W[(size_t)(k0 + wrow + 16) * N + n0 + wcol]);
        cpa16(&Bb[(wrow + 24) * 132 + wcol],    &W[(size_t)(k0 + wrow + 24) * N + n0 + wcol]);
    };

    load_tile(0, 0);
    CP_COMMIT();

    for (int k0 = 0; k0 < K; k0 += 32) {
        const int buf = (k0 >> 5) & 1;
        if (k0 + 32 < K) { load_tile(k0 + 32, buf ^ 1); CP_COMMIT(); CP_WAIT1(); }
        else             { CP_WAIT0(); }
        __syncthreads();

        const float* Ab = As + buf * GA_SZ;
        const float* Bb = Bs + buf * GB_SZ;
#pragma unroll
        for (int kk = 0; kk < 32; kk += 8) {
            wmma::fragment<wmma::matrix_a, 16, 16, 8, wmma::precision::tf32,
                           wmma::row_major> af[4];
            wmma::fragment<wmma::matrix_b, 16, 16, 8, wmma::precision::tf32,
                           wmma::row_major> bf[2];
#pragma unroll
            for (int i = 0; i < 4; i++) {
                wmma::load_matrix_sync(af[i], &Ab[(warp_m * 64 + i * 16) * 36 + kk], 36);
#pragma unroll
                for (int e = 0; e < af[i].num_elements; e++)
                    af[i].x[e] = wmma::__float_to_tf32(af[i].x[e]);
            }
#pragma unroll
            for (int j = 0; j < 2; j++) {
                wmma::load_matrix_sync(bf[j], &Bb[kk * 132 + warp_n * 32 + j * 16], 132);
#pragma unroll
                for (int e = 0; e < bf[j].num_elements; e++)
                    bf[j].x[e] = wmma::__float_to_tf32(bf[j].x[e]);
            }
#pragma unroll
            for (int i = 0; i < 4; i++)
#pragma unroll
                for (int j = 0; j < 2; j++)
                    wmma::mma_sync(acc[i][j], af[i], bf[j], acc[i][j]);
        }
        __syncthreads();
    }

#pragma unroll
    for (int i = 0; i < 4; i++)
#pragma unroll
        for (int j = 0; j < 2; j++)
            wmma::store_matrix_sync(
                &C[(size_t)(m0 + warp_m * 64 + i * 16) * N + n0 + warp_n * 32 + j * 16],
                acc[i][j], N, wmma::mem_row_major);
}

// ---------------- RoPE (in place) on [B,S,H,64]; freqs [S,32,2] ------------
__global__ void rope_kernel(float* __restrict__ X, const float* __restrict__ F,
                            int hshift, int total_pairs)
{
    int idx = blockIdx.x * blockDim.x + threadIdx.x;
    if (idx >= total_pairs) return;
    int p = idx & 31;
    int s = (idx >> (5 + hshift)) & (S_ - 1);
    float2 cs = ((const float2*)F)[s * 32 + p];
    float2 x  = ((float2*)X)[idx];
    float2 o;
    o.x = x.x * cs.x - x.y * cs.y;
    o.y = x.x * cs.y + x.y * cs.x;
    ((float2*)X)[idx] = o;
}

// ===================== GQA-fused TF32 flash attention ======================
// grid (S/32, KVH, B), 256 threads (8 warps).
// Q tile 128 rows = 4 q-heads x 32 seq rows, sharing one kv head's K/V.
// K/V tiles 64x64, double-buffered via cp.async.
#define ALD 72
#define KV_SZ (64 * ALD)
__global__ __launch_bounds__(256)
void attn_tf32(const float* __restrict__ Q, const float* __restrict__ K,
               const float* __restrict__ V, float* __restrict__ O)
{
    extern __shared__ float sm[];
    float* Qs = sm;                         // [128][72]
    float* Os = sm + 128 * ALD;             // [128][72]
    float* Sc = sm + 2 * 128 * ALD;         // [128][72] (scores / P)
    float* Ks = sm + 3 * 128 * ALD;         // [2][64][72]
    float* Vs = sm + 3 * 128 * ALD + 2 * KV_SZ; // [2][64][72]
    __shared__ float rowm[128], rowl[128], rowc[128];

    const int tid = threadIdx.x;
    const int w   = tid >> 5;
    const int kh  = blockIdx.y;
    const int b   = blockIdx.z;
    const int q0  = blockIdx.x * 32;

    // ---- load Q tile (4 heads x 32 rows), zero O ----
    for (int e4 = tid; e4 < 2048; e4 += 256) {
        int r = e4 >> 4, c4 = (e4 & 15) * 4;
        int h = (kh << 2) + (r >> 5);
        int srow = q0 + (r & 31);
        *(float4*)&Qs[r * ALD + c4] =
            *(const float4*)&Q[((size_t)(b * S_ + srow) * QH_ + h) * HD_ + c4];
        *(float4*)&Os[r * ALD + c4] = make_float4(0.f, 0.f, 0.f, 0.f);
    }
    if (tid < 128) { rowm[tid] = -1e30f; rowl[tid] = 0.f; }

    const float* kb = K + (size_t)b * S_ * KVH_ * HD_ + kh * HD_;
    const float* vb = V + (size_t)b * S_ * KVH_ * HD_ + kh * HD_;

    auto load_kv = [&](int kt, int buf) {
        float* Kb = Ks + buf * KV_SZ;
        float* Vb = Vs + buf * KV_SZ;
        const float* kp = kb + (size_t)kt * 64 * (KVH_ * HD_);
        const float* vp = vb + (size_t)kt * 64 * (KVH_ * HD_);
#pragma unroll
        for (int i = 0; i < 4; i++) {
            int e4 = tid + i * 256;                 // 0..1023
            int r = e4 >> 4, c4 = (e4 & 15) * 4;
            cpa16(&Kb[r * ALD + c4], &kp[(size_t)r * (KVH_ * HD_) + c4]);
            cpa16(&Vb[r * ALD + c4], &vp[(size_t)r * (KVH_ * HD_) + c4]);
        }
    };

    load_kv(0, 0);
    CP_COMMIT();

    for (int kt = 0; kt < S_ / 64; kt++) {
        const int buf = kt & 1;
        if (kt + 1 < S_ / 64) { load_kv(kt + 1, buf ^ 1); CP_COMMIT(); CP_WAIT1(); }
        else                  { CP_WAIT0(); }
        __syncthreads();

        const float* Kb = Ks + buf * KV_SZ;
        const float* Vb = Vs + buf * KV_SZ;

        // ---- S = Q K^T * scale : warp w -> rows w*16..+15, 64 cols ----
        {
            wmma::fragment<wmma::accumulator, 16, 16, 8, float> sacc[4];
#pragma unroll
            for (int j = 0; j < 4; j++) wmma::fill_fragment(sacc[j], 0.f);
#pragma unroll
            for (int kk = 0; kk < 64; kk += 8) {
                wmma::fragment<wmma::matrix_a, 16, 16, 8, wmma::precision::tf32,
                               wmma::row_major> af;
                wmma::load_matrix_sync(af, &Qs[w * 16 * ALD + kk], ALD);
#pragma unroll
                for (int e = 0; e < af.num_elements; e++)
                    af.x[e] = wmma::__float_to_tf32(af.x[e]);
#pragma unroll
                for (int j = 0; j < 4; j++) {
                    wmma::fragment<wmma::matrix_b, 16, 16, 8, wmma::precision::tf32,
                                   wmma::col_major> bf;
                    wmma::load_matrix_sync(bf, &Kb[j * 16 * ALD + kk], ALD);
#pragma unroll
                    for (int e = 0; e < bf.num_elements; e++)
                        bf.x[e] = wmma::__float_to_tf32(bf.x[e]);
                    wmma::mma_sync(sacc[j], af, bf, sacc[j]);
                }
            }
#pragma unroll
            for (int j = 0; j < 4; j++) {
#pragma unroll
                for (int e = 0; e < sacc[j].num_elements; e++)
                    sacc[j].x[e] *= 0.125f;
                wmma::store_matrix_sync(&Sc[w * 16 * ALD + j * 16], sacc[j], ALD,
                                        wmma::mem_row_major);
            }
        }
        __syncthreads();

        // ---- online softmax, one thread per row ----
        if (tid < 128) {
            float* rp = &Sc[tid * ALD];
            float tmax = -1e30f;
#pragma unroll
            for (int c = 0; c < 64; c++) tmax = fmaxf(tmax, rp[c]);
            float mold = rowm[tid];
            float mnew = fmaxf(mold, tmax);
            float corr = __expf(mold - mnew);
            float sum = 0.f;
#pragma unroll
            for (int c = 0; c < 64; c++) {
                float p = __expf(rp[c] - mnew);
                rp[c] = p;
                sum += p;
            }
            rowl[tid] = rowl[tid] * corr + sum;
            rowm[tid] = mnew;
            rowc[tid] = corr;
        }
        __syncthreads();

        // ---- rescale O ----
        for (int e4 = tid; e4 < 2048; e4 += 256) {
            int r = e4 >> 4, c4 = (e4 & 15) * 4;
            float cr = rowc[r];
            float4 o = *(float4*)&Os[r * ALD + c4];
            o.x *= cr; o.y *= cr; o.z *= cr; o.w *= cr;
            *(float4*)&Os[r * ALD + c4] = o;
        }
        __syncthreads();

        // ---- O += P V ----
        {
            wmma::fragment<wmma::accumulator, 16, 16, 8, float> oacc[4];
#pragma unroll
            for (int j = 0; j < 4; j++)
                wmma::load_matrix_sync(oacc[j], &Os[w * 16 * ALD + j * 16], ALD,
                                       wmma::mem_row_major);
#pragma unroll
            for (int kk = 0; kk < 64; kk += 8) {
                wmma::fragment<wmma::matrix_a, 16, 16, 8, wmma::precision::tf32,
                               wmma::row_major> af;
                wmma::load_matrix_sync(af, &Sc[w * 16 * ALD + kk], ALD);
#pragma unroll
                for (int e = 0; e < af.num_elements; e++)
                    af.x[e] = wmma::__float_to_tf32(af.x[e]);
#pragma unroll
                for (int j = 0; j < 4; j++) {
                    wmma::fragment<wmma::matrix_b, 16, 16, 8, wmma::precision::tf32,
                                   wmma::row_major> bf;
                    wmma::load_matrix_sync(bf, &Vb[kk * ALD + j * 16], ALD);
#pragma unroll
                    for (int e = 0; e < bf.num_elements; e++)
                        bf.x[e] = wmma::__float_to_tf32(bf.x[e]);
                    wmma::mma_sync(oacc[j], af, bf, oacc[j]);
                }
            }
#pragma unroll
            for (int j = 0; j < 4; j++)
                wmma::store_matrix_sync(&Os[w * 16 * ALD + j * 16], oacc[j], ALD,
                                        wmma::mem_row_major);
        }
        __syncthreads();
    }

    // ---- finalize ----
    for (int e4 = tid; e4 < 2048; e4 += 256) {
        int r = e4 >> 4, c4 = (e4 & 15) * 4;
        int h = (kh << 2) + (r >> 5);
        int srow = q0 + (r & 31);
        float inv = 1.0f / rowl[r];
        float4 o = *(float4*)&Os[r * ALD + c4];
        o.x *= inv; o.y *= inv; o.z *= inv; o.w *= inv;
        *(float4*)&O[((size_t)(b * S_ + srow) * QH_ + h) * HD_ + c4] = o;
    }
}

// ---------------------------------------------------------------------------
extern "C" void kernel_launch(void* const* d_in, const int* in_sizes, int n_in,
                              void* d_out, int out_size)
{
    const float* x  = (const float*)d_in[0];
    const float* fr = (const float*)d_in[1];
    const float* Wq = (const float*)d_in[2];
    const float* bq = (const float*)d_in[3];
    const float* Wk = (const float*)d_in[4];
    const float* bk = (const float*)d_in[5];
    const float* Wv = (const float*)d_in[6];
    const float* bv = (const float*)d_in[7];
    const float* Wo = (const float*)d_in[8];
    const float* bo = (const float*)d_in[9];
    float* out = (float*)d_out;

    float *Qp, *Kp, *Vp, *AOp;
    cudaGetSymbolAddress((void**)&Qp,  g_Q);
    cudaGetSymbolAddress((void**)&Kp,  g_K);
    cudaGetSymbolAddress((void**)&Vp,  g_V);
    cudaGetSymbolAddress((void**)&AOp, g_AO);

    const int M = B_ * S_;   // 4096

    const int gemm_smem = (2 * GA_SZ + 2 * GB_SZ) * sizeof(float);   // ~69 KB
    cudaFuncSetAttribute(gemm_tf32, cudaFuncAttributeMaxDynamicSharedMemorySize,
                         gemm_smem);

    gemm_tf32<<<dim3((QH_ * HD_) / 128, M / 128), 256, gemm_smem>>>(x, Wq, bq, Qp, M, QH_ * HD_, D_);
    gemm_tf32<<<dim3((KVH_ * HD_) / 128, M / 128), 256, gemm_smem>>>(x, Wk, bk, Kp, M, KVH_ * HD_, D_);
    gemm_tf32<<<dim3((KVH_ * HD_) / 128, M / 128), 256, gemm_smem>>>(x, Wv, bv, Vp, M, KVH_ * HD_, D_);

    {
        int totq = M * QH_ * 32;
        rope_kernel<<<totq / 256, 256>>>(Qp, fr, 5, totq);
        int totk = M * KVH_ * 32;
        rope_kernel<<<totk / 256, 256>>>(Kp, fr, 3, totk);
    }

    const int attn_smem = (3 * 128 * ALD + 4 * KV_SZ) * sizeof(float);  // ~184 KB
    cudaFuncSetAttribute(attn_tf32, cudaFuncAttributeMaxDynamicSharedMemorySize,
                         attn_smem);
    attn_tf32<<<dim3(S_ / 32, KVH_, B_), 256, attn_smem>>>(Qp, Kp, Vp, AOp);

    gemm_tf32<<<dim3(D_ / 128, M / 128), 256, gemm_smem>>>(AOp, Wo, bo, out, M, D_, D_);
}

// round 8
// speedup vs baseline: 2.2162x; 1.4342x over previous
#include <cuda_runtime.h>
#include <cstdint>
#include <mma.h>
#include <math.h>

using namespace nvcuda;

#define B_   2
#define S_   2048
#define D_   2048
#define QH_  32
#define KVH_ 8
#define HD_  64
#define GRP_ 4

// ---------------- scratch (no allocations allowed) ----------------
__device__ float g_Q [(size_t)B_ * S_ * QH_  * HD_];
__device__ float g_K [(size_t)B_ * S_ * KVH_ * HD_];
__device__ float g_V [(size_t)B_ * S_ * KVH_ * HD_];
__device__ float g_AO[(size_t)B_ * S_ * QH_  * HD_];

// ---------------- helpers ----------------
__device__ __forceinline__ void cpa16(void* smem_dst, const void* gmem_src) {
    unsigned d = (unsigned)__cvta_generic_to_shared(smem_dst);
    asm volatile("cp.async.cg.shared.global [%0], [%1], 16;\n" :: "r"(d), "l"(gmem_src));
}
#define CP_COMMIT() asm volatile("cp.async.commit_group;\n" ::: "memory")
#define CP_WAIT0()  asm volatile("cp.async.wait_group 0;\n" ::: "memory")
#define CP_WAIT1()  asm volatile("cp.async.wait_group 1;\n" ::: "memory")

__device__ __forceinline__ float tf32r(float x) {
    unsigned r; asm("cvt.rna.tf32.f32 %0, %1;" : "=r"(r) : "f"(x));
    return __uint_as_float(r);
}

__device__ __forceinline__ void mma16n8k8(float* d, const unsigned* a, const unsigned* b) {
    asm volatile(
        "mma.sync.aligned.m16n8k8.row.col.f32.tf32.tf32.f32 "
        "{%0,%1,%2,%3}, {%4,%5,%6,%7}, {%8,%9}, {%0,%1,%2,%3};"
        : "+f"(d[0]), "+f"(d[1]), "+f"(d[2]), "+f"(d[3])
        : "r"(a[0]), "r"(a[1]), "r"(a[2]), "r"(a[3]), "r"(b[0]), "r"(b[1]));
}

// ===================== TF32 GEMM + bias, double-buffered ===================
#define GA_SZ (128 * 36)
#define GB_SZ (32 * 132)
__global__ __launch_bounds__(256)
void gemm_tf32(const float* __restrict__ A, const float* __restrict__ W,
               const float* __restrict__ bias, float* __restrict__ C,
               int M, int N, int K)
{
    extern __shared__ float dsm[];
    float* As = dsm;
    float* Bs = dsm + 2 * GA_SZ;
    __shared__ float Bt[16 * 132];

    const int t      = threadIdx.x;
    const int warp   = t >> 5;
    const int warp_m = warp & 1;
    const int warp_n = warp >> 1;
    const int m0 = blockIdx.y * 128;
    const int n0 = blockIdx.x * 128;

    const int arow = t >> 2;
    const int avec = (t & 3) * 8;
    const int wrow = t >> 5;
    const int wcol = (t & 31) * 4;

    for (int e = t; e < 16 * 128; e += 256) {
        int r = e >> 7, c = e & 127;
        Bt[r * 132 + c] = bias[n0 + c];
    }

    wmma::fragment<wmma::accumulator, 16, 16, 8, float> acc[4][2];
    __syncthreads();
#pragma unroll
    for (int i = 0; i < 4; i++)
#pragma unroll
        for (int j = 0; j < 2; j++)
            wmma::load_matrix_sync(acc[i][j], &Bt[warp_n * 32 + j * 16], 132,
                                   wmma::mem_row_major);

    auto load_tile = [&](int k0, int buf) {
        float* Ab = As + buf * GA_SZ;
        float* Bb = Bs + buf * GB_SZ;
        cpa16(&Ab[arow * 36 + avec],            &A[(size_t)(m0 + arow)      * K + k0 + avec]);
        cpa16(&Ab[arow * 36 + avec + 4],        &A[(size_t)(m0 + arow)      * K + k0 + avec + 4]);
        cpa16(&Ab[(arow + 64) * 36 + avec],     &A[(size_t)(m0 + arow + 64) * K + k0 + avec]);
        cpa16(&Ab[(arow + 64) * 36 + avec + 4], &A[(size_t)(m0 + arow + 64) * K + k0 + avec + 4]);
        cpa16(&Bb[wrow * 132 + wcol],           &W[(size_t)(k0 + wrow)      * N + n0 + wcol]);
        cpa16(&Bb[(wrow +  8) * 132 + wcol],    &W[(size_t)(k0 + wrow +  8) * N + n0 + wcol]);
        cpa16(&Bb[(wrow + 16) * 132 + wcol],    &W[(size_t)(k0 + wrow + 16) * N + n0 + wcol]);
        cpa16(&Bb[(wrow + 24) * 132 + wcol],    &W[(size_t)(k0 + wrow + 24) * N + n0 + wcol]);
    };

    load_tile(0, 0);
    CP_COMMIT();

    for (int k0 = 0; k0 < K; k0 += 32) {
        const int buf = (k0 >> 5) & 1;
        if (k0 + 32 < K) { load_tile(k0 + 32, buf ^ 1); CP_COMMIT(); CP_WAIT1(); }
        else             { CP_WAIT0(); }
        __syncthreads();

        const float* Ab = As + buf * GA_SZ;
        const float* Bb = Bs + buf * GB_SZ;
#pragma unroll
        for (int kk = 0; kk < 32; kk += 8) {
            wmma::fragment<wmma::matrix_a, 16, 16, 8, wmma::precision::tf32,
                           wmma::row_major> af[4];
            wmma::fragment<wmma::matrix_b, 16, 16, 8, wmma::precision::tf32,
                           wmma::row_major> bf[2];
#pragma unroll
            for (int i = 0; i < 4; i++) {
                wmma::load_matrix_sync(af[i], &Ab[(warp_m * 64 + i * 16) * 36 + kk], 36);
#pragma unroll
                for (int e = 0; e < af[i].num_elements; e++)
                    af[i].x[e] = wmma::__float_to_tf32(af[i].x[e]);
            }
#pragma unroll
            for (int j = 0; j < 2; j++) {
                wmma::load_matrix_sync(bf[j], &Bb[kk * 132 + warp_n * 32 + j * 16], 132);
#pragma unroll
                for (int e = 0; e < bf[j].num_elements; e++)
                    bf[j].x[e] = wmma::__float_to_tf32(bf[j].x[e]);
            }
#pragma unroll
            for (int i = 0; i < 4; i++)
#pragma unroll
                for (int j = 0; j < 2; j++)
                    wmma::mma_sync(acc[i][j], af[i], bf[j], acc[i][j]);
        }
        __syncthreads();
    }

#pragma unroll
    for (int i = 0; i < 4; i++)
#pragma unroll
        for (int j = 0; j < 2; j++)
            wmma::store_matrix_sync(
                &C[(size_t)(m0 + warp_m * 64 + i * 16) * N + n0 + warp_n * 32 + j * 16],
                acc[i][j], N, wmma::mem_row_major);
}

// ---------------- RoPE (in place), outputs tf32-rounded --------------------
__global__ void rope_kernel(float* __restrict__ X, const float* __restrict__ F,
                            int hshift, int total_pairs)
{
    int idx = blockIdx.x * blockDim.x + threadIdx.x;
    if (idx >= total_pairs) return;
    int p = idx & 31;
    int s = (idx >> (5 + hshift)) & (S_ - 1);
    float2 cs = ((const float2*)F)[s * 32 + p];
    float2 x  = ((float2*)X)[idx];
    float2 o;
    o.x = tf32r(x.x * cs.x - x.y * cs.y);
    o.y = tf32r(x.x * cs.y + x.y * cs.x);
    ((float2*)X)[idx] = o;
}

// ---------------- round V to tf32 in place ---------------------------------
__global__ void vround_kernel(float* __restrict__ Vv)
{
    int idx = blockIdx.x * blockDim.x + threadIdx.x;
    float4 v = ((float4*)Vv)[idx];
    v.x = tf32r(v.x); v.y = tf32r(v.y); v.z = tf32r(v.z); v.w = tf32r(v.w);
    ((float4*)Vv)[idx] = v;
}

// ===================== FA2-style GQA attention (mma.sync tf32) =============
// grid (S/32, KVH, B), 256 threads / 8 warps. Warp w owns rows 16w..16w+15
// of the 128-row Q tile (4 q-heads x 32 seq rows). O accumulators + softmax
// state live in registers for the whole KV loop.
#define ALD 68
#define KV_SZ (64 * ALD)
__global__ __launch_bounds__(256)
void attn_mma(const float* __restrict__ Q, const float* __restrict__ K,
              const float* __restrict__ V, float* __restrict__ O)
{
    extern __shared__ float sm[];
    float* Qs = sm;                       // [128][68]  (also output staging)
    float* Sc = sm + 128 * ALD;           // [128][68]  P tile (warp-private rows)
    float* Ks = sm + 2 * 128 * ALD;       // [2][64][68]
    float* Vs = sm + 2 * 128 * ALD + 2 * KV_SZ;

    const int tid = threadIdx.x;
    const int w   = tid >> 5;
    const int l   = tid & 31;
    const int kh  = blockIdx.y;
    const int b   = blockIdx.z;
    const int q0  = blockIdx.x * 32;

    const int qr = l >> 2;     // quad row 0..7
    const int qc = l & 3;      // quad col 0..3
    const int row0 = 16 * w + qr;

    // ---- load Q tile (pre-scaled by 1/sqrt(64); already tf32-rounded) ----
    for (int e4 = tid; e4 < 2048; e4 += 256) {
        int r = e4 >> 4, c4 = (e4 & 15) * 4;
        int h = (kh << 2) + (r >> 5);
        int srow = q0 + (r & 31);
        float4 qv = *(const float4*)&Q[((size_t)(b * S_ + srow) * QH_ + h) * HD_ + c4];
        qv.x *= 0.125f; qv.y *= 0.125f; qv.z *= 0.125f; qv.w *= 0.125f;
        *(float4*)&Qs[r * ALD + c4] = qv;
    }

    const float* kb = K + (size_t)b * S_ * KVH_ * HD_ + kh * HD_;
    const float* vb = V + (size_t)b * S_ * KVH_ * HD_ + kh * HD_;

    auto load_kv = [&](int kt, int buf) {
        float* Kb = Ks + buf * KV_SZ;
        float* Vb = Vs + buf * KV_SZ;
        const float* kp = kb + (size_t)kt * 64 * (KVH_ * HD_);
        const float* vp = vb + (size_t)kt * 64 * (KVH_ * HD_);
#pragma unroll
        for (int i = 0; i < 4; i++) {
            int e4 = tid + i * 256;
            int r = e4 >> 4, c4 = (e4 & 15) * 4;
            cpa16(&Kb[r * ALD + c4], &kp[(size_t)r * (KVH_ * HD_) + c4]);
            cpa16(&Vb[r * ALD + c4], &vp[(size_t)r * (KVH_ * HD_) + c4]);
        }
    };

    float oacc[8][4];
#pragma unroll
    for (int j = 0; j < 8; j++)
#pragma unroll
        for (int e = 0; e < 4; e++) oacc[j][e] = 0.f;
    float m_a = -1e30f, m_b = -1e30f, l_a = 0.f, l_b = 0.f;

    load_kv(0, 0);
    CP_COMMIT();

    for (int kt = 0; kt < S_ / 64; kt++) {
        const int buf = kt & 1;
        CP_WAIT0();
        __syncthreads();
        if (kt + 1 < S_ / 64) { load_kv(kt + 1, buf ^ 1); CP_COMMIT(); }

        const float* Kb = Ks + buf * KV_SZ;
        const float* Vb = Vs + buf * KV_SZ;

        // ---- S = Q K^T (scaled Q), 16x64 per warp ----
        float sacc[8][4];
#pragma unroll
        for (int j = 0; j < 8; j++)
#pragma unroll
            for (int e = 0; e < 4; e++) sacc[j][e] = 0.f;

#pragma unroll
        for (int t = 0; t < 8; t++) {
            const int kc = t * 8;
            unsigned a[4];
            a[0] = __float_as_uint(Qs[(row0)     * ALD + kc + qc]);
            a[1] = __float_as_uint(Qs[(row0 + 8) * ALD + kc + qc]);
            a[2] = __float_as_uint(Qs[(row0)     * ALD + kc + qc + 4]);
            a[3] = __float_as_uint(Qs[(row0 + 8) * ALD + kc + qc + 4]);
#pragma unroll
            for (int j = 0; j < 8; j++) {
                unsigned bb[2];
                bb[0] = __float_as_uint(Kb[(8 * j + qr) * ALD + kc + qc]);
                bb[1] = __float_as_uint(Kb[(8 * j + qr) * ALD + kc + qc + 4]);
                mma16n8k8(sacc[j], a, bb);
            }
        }

        // ---- register softmax (rows qr/qr+8 of warp tile) ----
        float ma = -1e30f, mb = -1e30f;
#pragma unroll
        for (int j = 0; j < 8; j++) {
            ma = fmaxf(ma, fmaxf(sacc[j][0], sacc[j][1]));
            mb = fmaxf(mb, fmaxf(sacc[j][2], sacc[j][3]));
        }
        ma = fmaxf(ma, __shfl_xor_sync(0xffffffffu, ma, 1));
        ma = fmaxf(ma, __shfl_xor_sync(0xffffffffu, ma, 2));
        mb = fmaxf(mb, __shfl_xor_sync(0xffffffffu, mb, 1));
        mb = fmaxf(mb, __shfl_xor_sync(0xffffffffu, mb, 2));

        float na = fmaxf(m_a, ma), nb = fmaxf(m_b, mb);
        float ca = __expf(m_a - na), cb = __expf(m_b - nb);
        float sa = 0.f, sb = 0.f;

#pragma unroll
        for (int j = 0; j < 8; j++) {
            float p0 = __expf(sacc[j][0] - na);
            float p1 = __expf(sacc[j][1] - na);
            float p2 = __expf(sacc[j][2] - nb);
            float p3 = __expf(sacc[j][3] - nb);
            sa += p0 + p1; sb += p2 + p3;
            const int cc = 8 * j + 2 * qc;
            *(float2*)&Sc[(row0)     * ALD + cc] = make_float2(tf32r(p0), tf32r(p1));
            *(float2*)&Sc[(row0 + 8) * ALD + cc] = make_float2(tf32r(p2), tf32r(p3));
            oacc[j][0] *= ca; oacc[j][1] *= ca;
            oacc[j][2] *= cb; oacc[j][3] *= cb;
        }
        sa += __shfl_xor_sync(0xffffffffu, sa, 1);
        sa += __shfl_xor_sync(0xffffffffu, sa, 2);
        sb += __shfl_xor_sync(0xffffffffu, sb, 1);
        sb += __shfl_xor_sync(0xffffffffu, sb, 2);
        l_a = l_a * ca + sa;  m_a = na;
        l_b = l_b * cb + sb;  m_b = nb;
        __syncwarp();

        // ---- O += P V  (P warp-private in Sc) ----
#pragma unroll
        for (int t = 0; t < 8; t++) {
            const int kc = t * 8;
            unsigned a[4];
            a[0] = __float_as_uint(Sc[(row0)     * ALD + kc + qc]);
            a[1] = __float_as_uint(Sc[(row0 + 8) * ALD + kc + qc]);
            a[2] = __float_as_uint(Sc[(row0)     * ALD + kc + qc + 4]);
            a[3] = __float_as_uint(Sc[(row0 + 8) * ALD + kc + qc + 4]);
#pragma unroll
            for (int j = 0; j < 8; j++) {
                unsigned bb[2];
                bb[0] = __float_as_uint(Vb[(kc + qc)     * ALD + 8 * j + qr]);
                bb[1] = __float_as_uint(Vb[(kc + qc + 4) * ALD + 8 * j + qr]);
                mma16n8k8(oacc[j], a, bb);
            }
        }
        __syncwarp();
    }

    // ---- finalize: scale by 1/l, stage into Qs (own rows), coalesced out --
    const float ia = 1.0f / l_a, ib = 1.0f / l_b;
#pragma unroll
    for (int j = 0; j < 8; j++) {
        const int cc = 8 * j + 2 * qc;
        *(float2*)&Qs[(row0)     * ALD + cc] = make_float2(oacc[j][0] * ia, oacc[j][1] * ia);
        *(float2*)&Qs[(row0 + 8) * ALD + cc] = make_float2(oacc[j][2] * ib, oacc[j][3] * ib);
    }
    __syncwarp();
#pragma unroll
    for (int i = 0; i < 8; i++) {
        int e4 = l + i * 32;               // 0..255 over 16 rows x 16 float4
        int rr = e4 >> 4, c4 = (e4 & 15) * 4;
        int r = 16 * w + rr;
        int h = (kh << 2) + (r >> 5);
        int srow = q0 + (r & 31);
        *(float4*)&O[((size_t)(b * S_ + srow) * QH_ + h) * HD_ + c4] =
            *(float4*)&Qs[r * ALD + c4];
    }
}

// ---------------------------------------------------------------------------
extern "C" void kernel_launch(void* const* d_in, const int* in_sizes, int n_in,
                              void* d_out, int out_size)
{
    const float* x  = (const float*)d_in[0];
    const float* fr = (const float*)d_in[1];
    const float* Wq = (const float*)d_in[2];
    const float* bq = (const float*)d_in[3];
    const float* Wk = (const float*)d_in[4];
    const float* bk = (const float*)d_in[5];
    const float* Wv = (const float*)d_in[6];
    const float* bv = (const float*)d_in[7];
    const float* Wo = (const float*)d_in[8];
    const float* bo = (const float*)d_in[9];
    float* out = (float*)d_out;

    float *Qp, *Kp, *Vp, *AOp;
    cudaGetSymbolAddress((void**)&Qp,  g_Q);
    cudaGetSymbolAddress((void**)&Kp,  g_K);
    cudaGetSymbolAddress((void**)&Vp,  g_V);
    cudaGetSymbolAddress((void**)&AOp, g_AO);

    const int M = B_ * S_;   // 4096

    const int gemm_smem = (2 * GA_SZ + 2 * GB_SZ) * sizeof(float);
    cudaFuncSetAttribute(gemm_tf32, cudaFuncAttributeMaxDynamicSharedMemorySize,
                         gemm_smem);

    gemm_tf32<<<dim3((QH_ * HD_) / 128, M / 128), 256, gemm_smem>>>(x, Wq, bq, Qp, M, QH_ * HD_, D_);
    gemm_tf32<<<dim3((KVH_ * HD_) / 128, M / 128), 256, gemm_smem>>>(x, Wk, bk, Kp, M, KVH_ * HD_, D_);
    gemm_tf32<<<dim3((KVH_ * HD_) / 128, M / 128), 256, gemm_smem>>>(x, Wv, bv, Vp, M, KVH_ * HD_, D_);

    {
        int totq = M * QH_ * 32;
        rope_kernel<<<totq / 256, 256>>>(Qp, fr, 5, totq);
        int totk = M * KVH_ * 32;
        rope_kernel<<<totk / 256, 256>>>(Kp, fr, 3, totk);
        int v4 = (int)((size_t)B_ * S_ * KVH_ * HD_ / 4);
        vround_kernel<<<v4 / 256, 256>>>(Vp);
    }

    const int attn_smem = (2 * 128 * ALD + 4 * KV_SZ) * sizeof(float);  // ~136 KB
    cudaFuncSetAttribute(attn_mma, cudaFuncAttributeMaxDynamicSharedMemorySize,
                         attn_smem);
    attn_mma<<<dim3(S_ / 32, KVH_, B_), 256, attn_smem>>>(Qp, Kp, Vp, AOp);

    gemm_tf32<<<dim3(D_ / 128, M / 128), 256, gemm_smem>>>(AOp, Wo, bo, out, M, D_, D_);
}